// round 9
// baseline (speedup 1.0000x reference)
#include <cuda_runtime.h>
#include <math_constants.h>

#define BATCH 16
#define CH    512
#define HGT   128
#define WID   128
#define NS    8
#define GRID  (BATCH * CH)

// scratch (no allocs allowed). All zero-initialized at load; the last block
// resets everything it consumes, so each launch/replay starts from zeros.
__device__ int   g_rc[BATCH * HGT];   // per-(b,h) counts of elements == slice max
__device__ float g_F [BATCH * CH];    // per-(b,c) sum/W
__device__ unsigned int g_done;       // completed-block counter

// One block per (b,c) slice of 128x128 floats (64KB).
// 512 threads = 16 warps; warp w handles rows [w*8, w*8+8).
// Phase A: register-resident vector max+sum, single warp reduce, block reduce.
// Phase B: re-scan registers vs vmax; rare atomic per matching element.
// The LAST block runs the finalize: one warp per batch (16 warps = 16 batches).
__global__ __launch_bounds__(512) void fused_kernel(const float* __restrict__ x,
                                                    float* __restrict__ out) {
    const int bc   = blockIdx.x;          // 0..B*C-1
    const int b    = bc >> 9;             // / CH
    const int warp = threadIdx.x >> 5;    // 0..15
    const int lane = threadIdx.x & 31;

    const float4* base = reinterpret_cast<const float4*>(x) + (size_t)bc * (HGT * WID / 4);

    // Load 8 float4 (one per row) — independent, front-batched, streaming
    float4 v[8];
    #pragma unroll
    for (int r = 0; r < 8; r++) {
        v[r] = __ldcs(&base[(warp * 8 + r) * 32 + lane]);
    }

    // Vector sum and max trees (FMA pipe only, no shuffles)
    float4 s4 = v[0];
    float4 m4 = v[0];
    #pragma unroll
    for (int r = 1; r < 8; r++) {
        s4.x += v[r].x; s4.y += v[r].y; s4.z += v[r].z; s4.w += v[r].w;
        m4.x = fmaxf(m4.x, v[r].x); m4.y = fmaxf(m4.y, v[r].y);
        m4.z = fmaxf(m4.z, v[r].z); m4.w = fmaxf(m4.w, v[r].w);
    }
    float s = (s4.x + s4.y) + (s4.z + s4.w);
    float m = fmaxf(fmaxf(m4.x, m4.y), fmaxf(m4.z, m4.w));

    // Single warp reduce (10 shuffles total)
    #pragma unroll
    for (int off = 16; off > 0; off >>= 1) {
        s += __shfl_down_sync(0xffffffffu, s, off);
        m  = fmaxf(m, __shfl_down_sync(0xffffffffu, m, off));
    }

    __shared__ float s_wsum[16];
    __shared__ float s_wmax[16];
    __shared__ float s_vmax;
    __shared__ bool  s_last;
    if (lane == 0) { s_wsum[warp] = s; s_wmax[warp] = m; }
    __syncthreads();

    if (threadIdx.x == 0) {
        float tot = 0.0f, vm = -CUDART_INF_F;
        #pragma unroll
        for (int w = 0; w < 16; w++) { tot += s_wsum[w]; vm = fmaxf(vm, s_wmax[w]); }
        g_F[bc] = tot * (1.0f / (float)WID);
        s_vmax = vm;
    }
    __syncthreads();

    const float vmax = s_vmax;

    // Phase B: count elements equal to the global max, per row.
    // Typically exactly one element in the whole slice matches -> ~1 atomic/block.
    #pragma unroll
    for (int r = 0; r < 8; r++) {
        int c = (v[r].x == vmax) + (v[r].y == vmax) + (v[r].z == vmax) + (v[r].w == vmax);
        if (c) atomicAdd(&g_rc[b * HGT + warp * 8 + r], c);
    }

    // ---- last-block election (fence + atomic by thread 0 ONLY) ----
    // g_F[bc] was stored by thread 0 itself; g_rc updates are device-scope
    // L2 atomics; __syncthreads orders this block's work before the fence.
    __syncthreads();
    if (threadIdx.x == 0) {
        __threadfence();
        s_last = (atomicAdd(&g_done, 1u) == GRID - 1u);
    }
    __syncthreads();
    if (!s_last) return;

    // ================= fused finalize: warp w handles batch w ==============
    __shared__ int   s_Hc[16][HGT];
    __shared__ float s_hinv[16][NS];

    const int bb = warp;

    // Lane-parallel rc load (4 rows per lane) + reset for next replay.
    int rcv[4];
    #pragma unroll
    for (int i = 0; i < 4; i++) {
        const int idx = bb * HGT + lane * 4 + i;
        rcv[i] = g_rc[idx];
        g_rc[idx] = 0;
    }
    int l0 = rcv[0];
    int l1 = l0 + rcv[1];
    int l2 = l1 + rcv[2];
    int l3 = l2 + rcv[3];
    // warp exclusive scan of per-lane totals
    int basev = l3;
    #pragma unroll
    for (int off = 1; off < 32; off <<= 1) {
        int t = __shfl_up_sync(0xffffffffu, basev, off);
        if (lane >= off) basev += t;
    }
    basev -= l3;
    s_Hc[warp][lane * 4 + 0] = basev;
    s_Hc[warp][lane * 4 + 1] = basev + l0;
    s_Hc[warp][lane * 4 + 2] = basev + l1;
    s_Hc[warp][lane * 4 + 3] = basev + l2;
    __syncwarp();

    // Reference-exact sequential threshold scan (lane 0): only one k per j.
    if (lane == 0) {
        float hks[NS + 1];
        #pragma unroll
        for (int k = 0; k < NS; k++) hks[k] = 0.0f;
        hks[NS] = (float)HGT;

        int k = 1;
        #pragma unroll
        for (int j = 1; j <= HGT - 2; j++) {
            const int hj  = s_Hc[warp][j];
            const int hj1 = s_Hc[warp][j + 1];
            const int t   = k * (CH / NS);       // k*64
            if (k < NS && hj <= t && hj1 > t) {
                hks[k] = (float)j;
                k++;
            }
        }
        #pragma unroll
        for (int kk = 0; kk < NS; kk++)
            s_hinv[warp][kk] = 1.0f / (hks[kk + 1] - hks[kk]);
    }
    __syncwarp();

    // 4096 outputs per batch = 1024 float4; 32 lanes × 32 float4 each.
    const float4* F4 = reinterpret_cast<const float4*>(&g_F[bb * CH]);
    float4* ob = reinterpret_cast<float4*>(out + (size_t)bb * (NS * CH));
    #pragma unroll
    for (int i = 0; i < 32; i++) {
        const int idx4 = i * 32 + lane;          // 0..1023
        const int k    = idx4 >> 7;              // bin index
        const int c4   = idx4 & 127;             // float4 index within channels
        const float hi = s_hinv[warp][k];
        float4 f = F4[c4];
        f.x *= hi; f.y *= hi; f.z *= hi; f.w *= hi;
        ob[idx4] = f;
    }

    // reset counter for next launch/replay
    __syncthreads();
    if (threadIdx.x == 0) g_done = 0u;
}

extern "C" void kernel_launch(void* const* d_in, const int* in_sizes, int n_in,
                              void* d_out, int out_size) {
    const float* x = (const float*)d_in[0];
    float* out = (float*)d_out;

    fused_kernel<<<GRID, 512>>>(x, out);
}

// round 11
// speedup vs baseline: 1.2828x; 1.2828x over previous
#include <cuda_runtime.h>
#include <math_constants.h>

#define BATCH 16
#define CH    512
#define HGT   128
#define WID   128
#define NS    8

// scratch (no allocs allowed). g_rc is zero-initialized at load; finalize
// re-zeroes it after consuming, so every launch/replay starts from zeros.
__device__ int   g_rc[BATCH * HGT];   // per-(b,h) counts of elements == slice max
__device__ float g_F [BATCH * CH];    // per-(b,c) sum/W

// One block per (b,c) slice of 128x128 floats (64KB).
// 256 threads; thread (warp,lane) holds float4 of rows warp*16+r at column lane.
// Phase A: register-resident vector max+sum, single warp reduce, block reduce.
// Phase B: re-scan registers vs vmax; rare atomic per matching element.
__global__ __launch_bounds__(256) void pass1_kernel(const float* __restrict__ x) {
    const int bc   = blockIdx.x;          // 0..B*C-1
    const int b    = bc >> 9;             // / CH
    const int warp = threadIdx.x >> 5;
    const int lane = threadIdx.x & 31;

    const float4* base = reinterpret_cast<const float4*>(x) + (size_t)bc * (HGT * WID / 4);

    // Load all 16 float4 (one per row) — independent, front-batched
    float4 v[16];
    #pragma unroll
    for (int r = 0; r < 16; r++) {
        v[r] = base[(warp * 16 + r) * 32 + lane];
    }

    // Vector sum and max trees (FMA pipe only, no shuffles)
    float4 s4 = v[0];
    float4 m4 = v[0];
    #pragma unroll
    for (int r = 1; r < 16; r++) {
        s4.x += v[r].x; s4.y += v[r].y; s4.z += v[r].z; s4.w += v[r].w;
        m4.x = fmaxf(m4.x, v[r].x); m4.y = fmaxf(m4.y, v[r].y);
        m4.z = fmaxf(m4.z, v[r].z); m4.w = fmaxf(m4.w, v[r].w);
    }
    float s = (s4.x + s4.y) + (s4.z + s4.w);
    float m = fmaxf(fmaxf(m4.x, m4.y), fmaxf(m4.z, m4.w));

    // Single warp reduce (10 shuffles total)
    #pragma unroll
    for (int off = 16; off > 0; off >>= 1) {
        s += __shfl_down_sync(0xffffffffu, s, off);
        m  = fmaxf(m, __shfl_down_sync(0xffffffffu, m, off));
    }

    __shared__ float s_wsum[8];
    __shared__ float s_wmax[8];
    __shared__ float s_vmax;
    if (lane == 0) { s_wsum[warp] = s; s_wmax[warp] = m; }
    __syncthreads();

    if (threadIdx.x == 0) {
        float tot = 0.0f, vm = -CUDART_INF_F;
        #pragma unroll
        for (int w = 0; w < 8; w++) { tot += s_wsum[w]; vm = fmaxf(vm, s_wmax[w]); }
        g_F[bc] = tot * (1.0f / (float)WID);
        s_vmax = vm;
    }
    __syncthreads();

    const float vmax = s_vmax;

    // Phase B: count elements equal to the global max, per row.
    // Typically exactly one element in the whole slice matches -> ~1 atomic/block.
    #pragma unroll
    for (int r = 0; r < 16; r++) {
        int c = (v[r].x == vmax) + (v[r].y == vmax) + (v[r].z == vmax) + (v[r].w == vmax);
        if (c) atomicAdd(&g_rc[b * HGT + warp * 16 + r], c);
    }
}

// One block per batch, 128 threads (4 warps).
// Warp 0: lane-parallel rc load (+reset), 5-step warp-scan exclusive cumsum.
// Threshold scan parallelized EXACTLY (Hc non-decreasing => each threshold
// t_k=64k has a unique crossing j with Hc[j]<=t<Hc[j+1]):
//   - all 32 lanes run a fixed 7-step branchless binary search (lanes>=8
//     compute don't-cares but stay convergent),
//   - gating replicating the reference's single-forward-pointer semantics is
//     computed redundantly on ALL lanes with full-mask shuffles: k fires iff
//     k-1 fired at a strictly smaller j; a missing crossing kills later k.
__global__ __launch_bounds__(128) void finalize_kernel(float* __restrict__ out) {
    const int b    = blockIdx.x;
    const int lane = threadIdx.x & 31;

    __shared__ int   s_Hc[HGT];
    __shared__ float s_hinv[NS];

    if (threadIdx.x < 32) {
        // each lane owns rows lane*4 .. lane*4+3
        int rcv[4];
        #pragma unroll
        for (int i = 0; i < 4; i++) {
            const int idx = b * HGT + lane * 4 + i;
            rcv[i] = g_rc[idx];
            g_rc[idx] = 0;                 // reset for next launch/replay
        }
        int l0 = rcv[0];
        int l1 = l0 + rcv[1];
        int l2 = l1 + rcv[2];
        int l3 = l2 + rcv[3];
        // warp exclusive scan of per-lane totals
        int basev = l3;
        #pragma unroll
        for (int off = 1; off < 32; off <<= 1) {
            int t = __shfl_up_sync(0xffffffffu, basev, off);
            if (lane >= off) basev += t;
        }
        basev -= l3;
        s_Hc[lane * 4 + 0] = basev;
        s_Hc[lane * 4 + 1] = basev + l0;
        s_Hc[lane * 4 + 2] = basev + l1;
        s_Hc[lane * 4 + 3] = basev + l2;
        __syncwarp();

        // ---- convergent binary search on ALL lanes (7 fixed steps) ----
        // lane k (1..7) searches for its threshold; other lanes are don't-care
        const int t = lane * (CH / NS);              // 64*lane
        int lo = 1, hi = HGT - 2;                    // j in [1,126]
        #pragma unroll
        for (int step = 0; step < 7; step++) {
            const int mid = (lo + hi + 1) >> 1;
            const bool ge = (s_Hc[mid] <= t);
            lo = ge ? mid : lo;
            hi = ge ? hi : (mid - 1);
        }
        const bool ex = (s_Hc[lo] <= t) && (s_Hc[lo + 1] > t);
        const unsigned exmask = __ballot_sync(0xffffffffu, ex);

        // ---- sequential gating, replicated on all lanes (full-mask shfl) ----
        float hk_mine = (lane == NS) ? (float)HGT : 0.0f;   // bin edge owned by lane
        bool alive = true;
        int  prevc = 0;
        #pragma unroll
        for (int k = 1; k < NS; k++) {
            const int  ckk = __shfl_sync(0xffffffffu, lo, k);
            const bool ekk = (exmask >> k) & 1u;
            alive = alive && ekk && (ckk > prevc);
            if (alive) {
                if (lane == k) hk_mine = (float)ckk;
                prevc = ckk;
            }
        }

        // hsub[k] = hks[k+1] - hks[k]; lane k needs lane k+1's edge
        const float hk_next = __shfl_down_sync(0xffffffffu, hk_mine, 1);
        if (lane < NS) {
            s_hinv[lane] = 1.0f / (hk_next - hk_mine);
        }
    }
    __syncthreads();

    // 4096 outputs = 1024 float4; 128 threads × 8 float4 each. Pure FMUL.
    const float4* F4 = reinterpret_cast<const float4*>(&g_F[b * CH]);
    float4* ob = reinterpret_cast<float4*>(out + (size_t)b * (NS * CH));
    #pragma unroll
    for (int i = 0; i < 8; i++) {
        const int idx4 = i * 128 + threadIdx.x;      // 0..1023
        const int k    = idx4 >> 7;                  // bin index
        const int c4   = idx4 & 127;                 // float4 index within channels
        const float hi = s_hinv[k];
        float4 f = F4[c4];
        f.x *= hi; f.y *= hi; f.z *= hi; f.w *= hi;
        ob[idx4] = f;
    }
}

extern "C" void kernel_launch(void* const* d_in, const int* in_sizes, int n_in,
                              void* d_out, int out_size) {
    const float* x = (const float*)d_in[0];
    float* out = (float*)d_out;

    pass1_kernel<<<BATCH * CH, 256>>>(x);
    finalize_kernel<<<BATCH, 128>>>(out);
}